// round 13
// baseline (speedup 1.0000x reference)
#include <cuda_runtime.h>
#include <cuda_fp16.h>
#include <cstdint>

// Conv1d (valid cross-correlation) as implicit-im2col GEMM, fp16 mma.sync m16n8k16
// (fp32 accumulate). 4-deep cp.async ring + mbarrier producer/consumer, warps
// decoupled. This round: channels processed in PAIRS between waits (32 pipeline
// boundaries instead of 64; branch-free 128-MMA region per pair).
//
// x: [32, 64, 4096] f32   w: [128, 64, 64] f32   b: [128] f32
// out: [32, 128, 4033] f32,  out[n,f,t] = sum_c sum_j x[n,c,t+j] * w[f,c,j] + b[f]

#define N_BATCH 32
#define C_IN    64
#define W_IN    4096
#define F_OUT   128
#define WW      64
#define OUT_W   4033

#define M_BLK   128
#define XPAD    4352          // padded x row (t0max 3968 + 319 halo < 4352)
#define S_W     72            // half-stride per filter: u32 bank pattern 4q+r, conflict-free

#define W_TILE_B  (F_OUT * S_W * 2)          // 18432 B
#define X_TILE_B  (320 * 8)                  // 2560 B (uint2 quads)
#define RING_STRIDE (W_TILE_B + X_TILE_B)    // 20992 B
#define MB_OFF      (4 * RING_STRIDE)        // 83968: full[4] then empty[4]
#define SMEM_BYTES  (MB_OFF + 64)

__device__ __align__(16) half  g_wh[C_IN * F_OUT * WW];        // [c][f][j]  (1 MB)
__device__ __align__(16) uint2 g_xq[N_BATCH * C_IN * XPAD];    // quads (71 MB)
// g_xq[row][i] = { half2(x[i],x[i+1]), half2(x[i+8],x[i+9]) }

// ---- merged prep: blocks [0,2048) convert w; rest build x quads (4 pos/thread) ----
__global__ void prep_all(const float* __restrict__ w, const float* __restrict__ x) {
    int tid = threadIdx.x;
    int bid = blockIdx.x;
    if (bid < 2048) {
        int idx = bid * 256 + tid;                       // 524288 w elems
        int f = idx >> 12, c = (idx >> 6) & 63, j = idx & 63;
        g_wh[(((c << 7) | f) << 6) | j] = __float2half_rn(w[idx]);
    } else {
        int jb  = bid - 2048;                            // 5 blocks per row
        int row = jb / 5;                                // n*64 + c
        int i   = ((jb % 5) * 256 + tid) * 4;            // base position (mult of 4)
        if (i < XPAD) {
            const float* xr = x + (size_t)row * W_IN;
            float v[13];
            if (i + 16 <= W_IN) {
                float4 a = *(const float4*)(xr + i);
                float4 c4 = *(const float4*)(xr + i + 4);
                float4 d4 = *(const float4*)(xr + i + 8);
                v[0]=a.x; v[1]=a.y; v[2]=a.z; v[3]=a.w;
                v[4]=c4.x; v[5]=c4.y; v[6]=c4.z; v[7]=c4.w;
                v[8]=d4.x; v[9]=d4.y; v[10]=d4.z; v[11]=d4.w;
                v[12]=xr[i + 12];
            } else {
                #pragma unroll
                for (int k = 0; k < 13; ++k)
                    v[k] = (i + k < W_IN) ? xr[i + k] : 0.f;
            }
            uint4 o0, o1;
            {
                __half2 p0 = __floats2half2_rn(v[0], v[1]);
                __half2 p8 = __floats2half2_rn(v[8], v[9]);
                __half2 q0 = __floats2half2_rn(v[1], v[2]);
                __half2 q8 = __floats2half2_rn(v[9], v[10]);
                o0.x = *(unsigned*)&p0; o0.y = *(unsigned*)&p8;
                o0.z = *(unsigned*)&q0; o0.w = *(unsigned*)&q8;
            }
            {
                __half2 p0 = __floats2half2_rn(v[2], v[3]);
                __half2 p8 = __floats2half2_rn(v[10], v[11]);
                __half2 q0 = __floats2half2_rn(v[3], v[4]);
                __half2 q8 = __floats2half2_rn(v[11], v[12]);
                o1.x = *(unsigned*)&p0; o1.y = *(unsigned*)&p8;
                o1.z = *(unsigned*)&q0; o1.w = *(unsigned*)&q8;
            }
            uint4* dst = (uint4*)(g_xq + (size_t)row * XPAD + i);
            dst[0] = o0;
            dst[1] = o1;
        }
    }
}

// ---- async copy + mbarrier primitives ----
__device__ __forceinline__ void cpa16(uint32_t dst, const void* src) {
    asm volatile("cp.async.cg.shared.global [%0], [%1], 16;" :: "r"(dst), "l"(src) : "memory");
}
#define MBAR_INIT(addr, cnt) \
    asm volatile("mbarrier.init.shared.b64 [%0], %1;" :: "r"(addr), "r"(cnt) : "memory")
#define MBAR_ARRIVE(addr) \
    asm volatile("mbarrier.arrive.shared.b64 _, [%0];" :: "r"(addr) : "memory")
#define CP_MBAR_ARRIVE(addr) \
    asm volatile("cp.async.mbarrier.arrive.noinc.shared.b64 [%0];" :: "r"(addr) : "memory")

__device__ __forceinline__ void mbar_wait(uint32_t addr, uint32_t parity) {
    uint32_t done;
    asm volatile(
        "{\n\t.reg .pred p;\n\t"
        "mbarrier.try_wait.parity.shared.b64 p, [%1], %2;\n\t"
        "selp.b32 %0, 1, 0, p;\n\t}"
        : "=r"(done) : "r"(addr), "r"(parity) : "memory");
    if (!done) {
        asm volatile(
            "{\n\t.reg .pred P1;\n\t"
            "W_%=:\n\t"
            "mbarrier.try_wait.parity.shared.b64 P1, [%0], %1;\n\t"
            "@P1 bra.uni D_%=;\n\t"
            "bra.uni W_%=;\n\t"
            "D_%=:\n\t}"
            :: "r"(addr), "r"(parity) : "memory");
    }
}

__global__ __launch_bounds__(256, 2)
void conv1d_main(const float* __restrict__ b, float* __restrict__ out)
{
    extern __shared__ __align__(16) char dsm[];
    const uint32_t smb = (uint32_t)__cvta_generic_to_shared(dsm);

    const int tid  = threadIdx.x;
    const int lane = tid & 31;
    const int warp = tid >> 5;
    const int wm   = warp & 1;        // 2 warps along t -> 64 rows each
    const int wn   = warp >> 1;       // 4 warps along f -> 32 cols each
    const int n    = blockIdx.y;
    const int t0   = blockIdx.x * M_BLK;

    const int q = lane >> 2;          // 0..7
    const int r = lane & 3;           // 0..3
    const int m_base = wm * 64;
    const int n_base = wn * 32;

    float acc[4][4][4];
    #pragma unroll
    for (int i = 0; i < 4; i++)
        #pragma unroll
        for (int j = 0; j < 4; j++)
            #pragma unroll
            for (int k = 0; k < 4; k++) acc[i][j][k] = 0.f;

    const uint2* xsrc_base = g_xq + (size_t)(n * C_IN) * XPAD + t0;

    // mbarriers: full[s] = staged data ready (cp.async thread-arrivals, noinc),
    //            empty[s] = all 8 warps done computing (8 arrivals)
    if (tid == 0) {
        #pragma unroll
        for (int s = 0; s < 4; ++s) {
            MBAR_INIT(smb + MB_OFF + s * 8, 256);
            MBAR_INIT(smb + MB_OFF + 32 + s * 8, 8);
        }
    }
    __syncthreads();   // the ONLY block-wide barrier

    auto stage = [&](int c, int s) {
        const half* wsrc = g_wh + ((size_t)c << 13);          // c * 8192 halves
        uint32_t base = smb + (uint32_t)s * RING_STRIDE;
        #pragma unroll
        for (int i = 0; i < 4; ++i) {
            int cidx = tid + (i << 8);                        // 0..1023 16-byte chunks
            int f = cidx >> 3, j16 = cidx & 7;
            cpa16(base + (uint32_t)(f * (S_W * 2) + j16 * 16), wsrc + f * 64 + j16 * 8);
        }
        if (tid < 160)
            cpa16(base + W_TILE_B + tid * 16,
                  (const char*)(xsrc_base + (size_t)c * XPAD) + tid * 16);
        CP_MBAR_ARRIVE(smb + MB_OFF + s * 8);
    };

    auto compute = [&](const char* bufc) {
        const half*  ws = (const half*)bufc;
        const uint2* xa = (const uint2*)(bufc + W_TILE_B);
        #pragma unroll
        for (int j0 = 0; j0 < WW; j0 += 16) {
            unsigned bb[4][2];
            #pragma unroll
            for (int nt = 0; nt < 4; ++nt) {
                const unsigned* wp =
                    (const unsigned*)(ws + (n_base + nt * 8 + q) * S_W + j0 + 2 * r);
                bb[nt][0] = wp[0];       // taps j0+2r, j0+2r+1
                bb[nt][1] = wp[4];       // taps j0+2r+8, j0+2r+9
            }
            #pragma unroll
            for (int mt = 0; mt < 4; ++mt) {
                int row = m_base + mt * 16 + q;
                uint2 p01 = xa[row + j0 + 2 * r];        // {pair(i), pair(i+8)}
                uint2 p23 = xa[row + j0 + 2 * r + 8];
                #pragma unroll
                for (int nt = 0; nt < 4; ++nt) {
                    asm volatile(
                        "mma.sync.aligned.m16n8k16.row.col.f32.f16.f16.f32 "
                        "{%0,%1,%2,%3}, {%4,%5,%6,%7}, {%8,%9}, {%0,%1,%2,%3};\n"
                        : "+f"(acc[mt][nt][0]), "+f"(acc[mt][nt][1]),
                          "+f"(acc[mt][nt][2]), "+f"(acc[mt][nt][3])
                        : "r"(p01.x), "r"(p01.y), "r"(p23.x), "r"(p23.y),
                          "r"(bb[nt][0]), "r"(bb[nt][1]));
                }
            }
        }
    };

    stage(0, 0);
    stage(1, 1);
    stage(2, 2);

    for (int p = 0; p < C_IN / 2; ++p) {
        const int c0 = 2 * p, c1 = c0 + 1;

        mbar_wait(smb + MB_OFF + (c0 & 3) * 8, (c0 >> 2) & 1);
        mbar_wait(smb + MB_OFF + (c1 & 3) * 8, (c1 >> 2) & 1);

        // branch-free 2-channel compute region (128 MMAs)
        compute(dsm + (c0 & 3) * RING_STRIDE);
        compute(dsm + (c1 & 3) * RING_STRIDE);

        if (lane == 0) {
            MBAR_ARRIVE(smb + MB_OFF + 32 + (c0 & 3) * 8);
            MBAR_ARRIVE(smb + MB_OFF + 32 + (c1 & 3) * 8);
        }

        // stage c0+3 (slot last held c0-1) and c0+4 (slot last held c0)
        const int cA = c0 + 3;
        if (cA < C_IN) {
            if (cA >= 4)
                mbar_wait(smb + MB_OFF + 32 + (cA & 3) * 8, ((cA - 4) >> 2) & 1);
            stage(cA, cA & 3);
        }
        const int cB = c0 + 4;
        if (cB < C_IN) {
            mbar_wait(smb + MB_OFF + 32 + (cB & 3) * 8, ((cB - 4) >> 2) & 1);
            stage(cB, cB & 3);
        }
    }

    // ---- epilogue: acc + bias -> out[n][f][t] ----
    float* outn = out + (size_t)n * F_OUT * OUT_W;
    #pragma unroll
    for (int mt = 0; mt < 4; ++mt) {
        int trow = t0 + m_base + mt * 16 + q;
        #pragma unroll
        for (int nt = 0; nt < 4; ++nt) {
            int f0 = n_base + nt * 8 + r * 2;
            float bias0 = __ldg(b + f0);
            float bias1 = __ldg(b + f0 + 1);
            if (trow < OUT_W) {
                outn[(size_t)f0       * OUT_W + trow] = acc[mt][nt][0] + bias0;
                outn[(size_t)(f0 + 1) * OUT_W + trow] = acc[mt][nt][1] + bias1;
            }
            if (trow + 8 < OUT_W) {
                outn[(size_t)f0       * OUT_W + trow + 8] = acc[mt][nt][2] + bias0;
                outn[(size_t)(f0 + 1) * OUT_W + trow + 8] = acc[mt][nt][3] + bias1;
            }
        }
    }
}

extern "C" void kernel_launch(void* const* d_in, const int* in_sizes, int n_in,
                              void* d_out, int out_size)
{
    const float* x = (const float*)d_in[0];
    const float* w = (const float*)d_in[1];
    const float* b = (const float*)d_in[2];
    float* out = (float*)d_out;

    prep_all<<<2048 + 2048 * 5, 256>>>(w, x);

    cudaFuncSetAttribute(conv1d_main,
                         cudaFuncAttributeMaxDynamicSharedMemorySize, SMEM_BYTES);
    dim3 grid(W_IN / M_BLK, N_BATCH);    // 32 x 32
    conv1d_main<<<grid, 256, SMEM_BYTES>>>(b, out);
}

// round 14
// speedup vs baseline: 1.1182x; 1.1182x over previous
#include <cuda_runtime.h>
#include <cuda_fp16.h>
#include <cstdint>

// Conv1d (valid cross-correlation) as implicit-im2col GEMM, fp16 mma.sync m16n8k16
// (fp32 accumulate). 4-deep cp.async ring + mbarrier producer/consumer, warps
// decoupled. This round: full-wait for channel c+1 hoisted into the middle of
// channel c's compute, so the LDS->MMA refill of c+1 overlaps the MMA drain of c.
//
// x: [32, 64, 4096] f32   w: [128, 64, 64] f32   b: [128] f32
// out: [32, 128, 4033] f32,  out[n,f,t] = sum_c sum_j x[n,c,t+j] * w[f,c,j] + b[f]

#define N_BATCH 32
#define C_IN    64
#define W_IN    4096
#define F_OUT   128
#define WW      64
#define OUT_W   4033

#define M_BLK   128
#define XPAD    4352          // padded x row (t0max 3968 + 319 halo < 4352)
#define S_W     72            // half-stride per filter: u32 bank pattern 4q+r, conflict-free

#define W_TILE_B  (F_OUT * S_W * 2)          // 18432 B
#define X_TILE_B  (320 * 8)                  // 2560 B (uint2 quads)
#define RING_STRIDE (W_TILE_B + X_TILE_B)    // 20992 B
#define MB_OFF      (4 * RING_STRIDE)        // 83968: full[4] then empty[4]
#define SMEM_BYTES  (MB_OFF + 64)

__device__ __align__(16) half  g_wh[C_IN * F_OUT * WW];        // [c][f][j]  (1 MB)
__device__ __align__(16) uint2 g_xq[N_BATCH * C_IN * XPAD];    // quads (71 MB)
// g_xq[row][i] = { half2(x[i],x[i+1]), half2(x[i+8],x[i+9]) }

// ---- merged prep: blocks [0,2048) convert w; rest build x quads (4 pos/thread) ----
__global__ void prep_all(const float* __restrict__ w, const float* __restrict__ x) {
    int tid = threadIdx.x;
    int bid = blockIdx.x;
    if (bid < 2048) {
        int idx = bid * 256 + tid;                       // 524288 w elems
        int f = idx >> 12, c = (idx >> 6) & 63, j = idx & 63;
        g_wh[(((c << 7) | f) << 6) | j] = __float2half_rn(w[idx]);
    } else {
        int jb  = bid - 2048;                            // 5 blocks per row
        int row = jb / 5;                                // n*64 + c
        int i   = ((jb % 5) * 256 + tid) * 4;            // base position (mult of 4)
        if (i < XPAD) {
            const float* xr = x + (size_t)row * W_IN;
            float v[13];
            if (i + 16 <= W_IN) {
                float4 a = *(const float4*)(xr + i);
                float4 c4 = *(const float4*)(xr + i + 4);
                float4 d4 = *(const float4*)(xr + i + 8);
                v[0]=a.x; v[1]=a.y; v[2]=a.z; v[3]=a.w;
                v[4]=c4.x; v[5]=c4.y; v[6]=c4.z; v[7]=c4.w;
                v[8]=d4.x; v[9]=d4.y; v[10]=d4.z; v[11]=d4.w;
                v[12]=xr[i + 12];
            } else {
                #pragma unroll
                for (int k = 0; k < 13; ++k)
                    v[k] = (i + k < W_IN) ? xr[i + k] : 0.f;
            }
            uint4 o0, o1;
            {
                __half2 p0 = __floats2half2_rn(v[0], v[1]);
                __half2 p8 = __floats2half2_rn(v[8], v[9]);
                __half2 q0 = __floats2half2_rn(v[1], v[2]);
                __half2 q8 = __floats2half2_rn(v[9], v[10]);
                o0.x = *(unsigned*)&p0; o0.y = *(unsigned*)&p8;
                o0.z = *(unsigned*)&q0; o0.w = *(unsigned*)&q8;
            }
            {
                __half2 p0 = __floats2half2_rn(v[2], v[3]);
                __half2 p8 = __floats2half2_rn(v[10], v[11]);
                __half2 q0 = __floats2half2_rn(v[3], v[4]);
                __half2 q8 = __floats2half2_rn(v[11], v[12]);
                o1.x = *(unsigned*)&p0; o1.y = *(unsigned*)&p8;
                o1.z = *(unsigned*)&q0; o1.w = *(unsigned*)&q8;
            }
            uint4* dst = (uint4*)(g_xq + (size_t)row * XPAD + i);
            dst[0] = o0;
            dst[1] = o1;
        }
    }
}

// ---- async copy + mbarrier primitives ----
__device__ __forceinline__ void cpa16(uint32_t dst, const void* src) {
    asm volatile("cp.async.cg.shared.global [%0], [%1], 16;" :: "r"(dst), "l"(src) : "memory");
}
#define MBAR_INIT(addr, cnt) \
    asm volatile("mbarrier.init.shared.b64 [%0], %1;" :: "r"(addr), "r"(cnt) : "memory")
#define MBAR_ARRIVE(addr) \
    asm volatile("mbarrier.arrive.shared.b64 _, [%0];" :: "r"(addr) : "memory")
#define CP_MBAR_ARRIVE(addr) \
    asm volatile("cp.async.mbarrier.arrive.noinc.shared.b64 [%0];" :: "r"(addr) : "memory")

__device__ __forceinline__ void mbar_wait(uint32_t addr, uint32_t parity) {
    uint32_t done;
    asm volatile(
        "{\n\t.reg .pred p;\n\t"
        "mbarrier.try_wait.parity.shared.b64 p, [%1], %2;\n\t"
        "selp.b32 %0, 1, 0, p;\n\t}"
        : "=r"(done) : "r"(addr), "r"(parity) : "memory");
    if (!done) {
        asm volatile(
            "{\n\t.reg .pred P1;\n\t"
            "W_%=:\n\t"
            "mbarrier.try_wait.parity.shared.b64 P1, [%0], %1;\n\t"
            "@P1 bra.uni D_%=;\n\t"
            "bra.uni W_%=;\n\t"
            "D_%=:\n\t}"
            :: "r"(addr), "r"(parity) : "memory");
    }
}

__global__ __launch_bounds__(256, 2)
void conv1d_main(const float* __restrict__ b, float* __restrict__ out)
{
    extern __shared__ __align__(16) char dsm[];
    const uint32_t smb = (uint32_t)__cvta_generic_to_shared(dsm);

    const int tid  = threadIdx.x;
    const int lane = tid & 31;
    const int warp = tid >> 5;
    const int wm   = warp & 1;        // 2 warps along t -> 64 rows each
    const int wn   = warp >> 1;       // 4 warps along f -> 32 cols each
    const int n    = blockIdx.y;
    const int t0   = blockIdx.x * M_BLK;

    const int q = lane >> 2;          // 0..7
    const int r = lane & 3;           // 0..3
    const int m_base = wm * 64;
    const int n_base = wn * 32;

    float acc[4][4][4];
    #pragma unroll
    for (int i = 0; i < 4; i++)
        #pragma unroll
        for (int j = 0; j < 4; j++)
            #pragma unroll
            for (int k = 0; k < 4; k++) acc[i][j][k] = 0.f;

    const uint2* xsrc_base = g_xq + (size_t)(n * C_IN) * XPAD + t0;

    // mbarriers: full[s] = staged data ready (cp.async thread-arrivals, noinc),
    //            empty[s] = all 8 warps done computing (8 arrivals)
    if (tid == 0) {
        #pragma unroll
        for (int s = 0; s < 4; ++s) {
            MBAR_INIT(smb + MB_OFF + s * 8, 256);
            MBAR_INIT(smb + MB_OFF + 32 + s * 8, 8);
        }
    }
    __syncthreads();   // the ONLY block-wide barrier

    auto stage = [&](int c, int s) {
        const half* wsrc = g_wh + ((size_t)c << 13);          // c * 8192 halves
        uint32_t base = smb + (uint32_t)s * RING_STRIDE;
        #pragma unroll
        for (int i = 0; i < 4; ++i) {
            int cidx = tid + (i << 8);                        // 0..1023 16-byte chunks
            int f = cidx >> 3, j16 = cidx & 7;
            cpa16(base + (uint32_t)(f * (S_W * 2) + j16 * 16), wsrc + f * 64 + j16 * 8);
        }
        if (tid < 160)
            cpa16(base + W_TILE_B + tid * 16,
                  (const char*)(xsrc_base + (size_t)c * XPAD) + tid * 16);
        CP_MBAR_ARRIVE(smb + MB_OFF + s * 8);
    };

    stage(0, 0);
    stage(1, 1);
    stage(2, 2);

    mbar_wait(smb + MB_OFF + 0, 0);                 // full(0)

    for (int c = 0; c < C_IN; ++c) {
        const char*  bufc = dsm + (c & 3) * RING_STRIDE;
        const half*  ws   = (const half*)bufc;
        const uint2* xa   = (const uint2*)(bufc + W_TILE_B);

        #pragma unroll
        for (int j0 = 0; j0 < WW; j0 += 16) {
            // hoisted wait: full(c+1) checked mid-channel, overlapping c's MMA queue
            if (j0 == 32 && c + 1 < C_IN)
                mbar_wait(smb + MB_OFF + ((c + 1) & 3) * 8, ((c + 1) >> 2) & 1);

            unsigned bb[4][2];
            #pragma unroll
            for (int nt = 0; nt < 4; ++nt) {
                const unsigned* wp =
                    (const unsigned*)(ws + (n_base + nt * 8 + q) * S_W + j0 + 2 * r);
                bb[nt][0] = wp[0];       // taps j0+2r, j0+2r+1
                bb[nt][1] = wp[4];       // taps j0+2r+8, j0+2r+9
            }
            #pragma unroll
            for (int mt = 0; mt < 4; ++mt) {
                int row = m_base + mt * 16 + q;
                uint2 p01 = xa[row + j0 + 2 * r];        // {pair(i), pair(i+8)}
                uint2 p23 = xa[row + j0 + 2 * r + 8];
                #pragma unroll
                for (int nt = 0; nt < 4; ++nt) {
                    asm volatile(
                        "mma.sync.aligned.m16n8k16.row.col.f32.f16.f16.f32 "
                        "{%0,%1,%2,%3}, {%4,%5,%6,%7}, {%8,%9}, {%0,%1,%2,%3};\n"
                        : "+f"(acc[mt][nt][0]), "+f"(acc[mt][nt][1]),
                          "+f"(acc[mt][nt][2]), "+f"(acc[mt][nt][3])
                        : "r"(p01.x), "r"(p01.y), "r"(p23.x), "r"(p23.y),
                          "r"(bb[nt][0]), "r"(bb[nt][1]));
                }
            }
        }

        if (lane == 0) MBAR_ARRIVE(smb + MB_OFF + 32 + (c & 3) * 8);  // warp done(c)

        // stage channel c+3 into slot (c+3)&3 == (c-1)&3 (last used by channel c-1)
        if (c + 3 < C_IN) {
            if (c >= 1)   // wait: all warps done with channel c-1 (distance-1 slack)
                mbar_wait(smb + MB_OFF + 32 + ((c + 3) & 3) * 8, ((c - 1) >> 2) & 1);
            stage(c + 3, (c + 3) & 3);
        }
    }

    // ---- epilogue: acc + bias -> out[n][f][t] ----
    float* outn = out + (size_t)n * F_OUT * OUT_W;
    #pragma unroll
    for (int mt = 0; mt < 4; ++mt) {
        int trow = t0 + m_base + mt * 16 + q;
        #pragma unroll
        for (int nt = 0; nt < 4; ++nt) {
            int f0 = n_base + nt * 8 + r * 2;
            float bias0 = __ldg(b + f0);
            float bias1 = __ldg(b + f0 + 1);
            if (trow < OUT_W) {
                outn[(size_t)f0       * OUT_W + trow] = acc[mt][nt][0] + bias0;
                outn[(size_t)(f0 + 1) * OUT_W + trow] = acc[mt][nt][1] + bias1;
            }
            if (trow + 8 < OUT_W) {
                outn[(size_t)f0       * OUT_W + trow + 8] = acc[mt][nt][2] + bias0;
                outn[(size_t)(f0 + 1) * OUT_W + trow + 8] = acc[mt][nt][3] + bias1;
            }
        }
    }
}

extern "C" void kernel_launch(void* const* d_in, const int* in_sizes, int n_in,
                              void* d_out, int out_size)
{
    const float* x = (const float*)d_in[0];
    const float* w = (const float*)d_in[1];
    const float* b = (const float*)d_in[2];
    float* out = (float*)d_out;

    prep_all<<<2048 + 2048 * 5, 256>>>(w, x);

    cudaFuncSetAttribute(conv1d_main,
                         cudaFuncAttributeMaxDynamicSharedMemorySize, SMEM_BYTES);
    dim3 grid(W_IN / M_BLK, N_BATCH);    // 32 x 32
    conv1d_main<<<grid, 256, SMEM_BYTES>>>(b, out);
}